// round 13
// baseline (speedup 1.0000x reference)
#include <cuda_runtime.h>
#include <cuda_fp16.h>
#include <mma.h>
#include <cstdint>

using namespace nvcuda;

// DynamicConv: B=64, CIN=COUT=256, K=4 experts, 3x3 kernel on (L=1024 x 1).
// Width==1 + padding 1 => only kw=1 column contributes: per-batch GEMM
//   C[o,h] = sum_{ci,kh} Wagg[b][o,ci,kh] * x[b][ci,h-1+kh]   (M=256,N=1024,K=768)
// R12: conv reverted to proven R10 shape (8 warps, 32x64 tiles, 2 CTA/SM,
//      triple-buffered A). Routing MLP fused into mix_kernel (2 launches total);
//      conv mixes bias inline from g_att.

#define BATCH   64
#define CIN     256
#define COUT    256
#define CS      256
#define KEXP    4
#define HIDDEN  64
#define LEN     1024
#define TEMP    30.0f

#define TM      128            // o per CTA
#define TN      128            // h per CTA
#define CCH     64             // ci per K-chunk
#define NCB     (CIN / CCH)    // 4
#define NTILE   (3 * NCB)      // 12

#define ASTR    72             // fp16 A row stride (144 B)
#define BSTR    72             // fp16 B row stride
#define BBSTR   24             // bias tile stride
#define XW      132            // x_s row width (floats): 0..127 body, 128 R-halo, 129 L-halo

// SMEM layout (bytes)
#define SM_ABUF(i) ((uint32_t)(18432u * (i)))   // 3 x 128x144
#define SM_B     55296          // B 136x144 = 19584
#define SM_X     74880          // x_s 64x132x4 = 33792
#define SM_TOTAL 108672
// bias tiles overlay B region (pre-mainloop only)
#define SM_ABH   SM_B
#define SM_BB    (SM_B + 6144)

__device__ float g_att[BATCH * KEXP];
// Wagg fp16: [b][kh][cbi][o(256)][ci(64)]
#define WA_BSTRIDE (3 * NCB * COUT * CCH)   // 196608
__device__ __half g_wa[BATCH * WA_BSTRIDE];

__device__ __forceinline__ uint32_t smem_u32(const void* p) {
    uint32_t a;
    asm("{ .reg .u64 t; cvta.to.shared.u64 t, %1; cvt.u32.u64 %0, t; }" : "=r"(a) : "l"(p));
    return a;
}
__device__ __forceinline__ void cpa16(uint32_t d, const void* s) {
    asm volatile("cp.async.cg.shared.global [%0], [%1], 16;" :: "r"(d), "l"(s));
}
#define CP_COMMIT()  asm volatile("cp.async.commit_group;" ::: "memory")
#define CP_WAIT(n)   asm volatile("cp.async.wait_group %0;" :: "n"(n) : "memory")

// ---------------------------------------------------------------------------
// Kernel 1: fused routing (redundant per block) + expert weight mixing.
// grid 96 x 256. Each block computes att[64][4] locally (~1M FMA, ~4us wall,
// parallel across blocks); block 0 publishes g_att for the conv kernel.
// Then mixes weights: thread = (kh,cbi,o,8-ci group), 16B coalesced stores.
// ---------------------------------------------------------------------------
__global__ void mix_kernel(const float* __restrict__ weight,
                           const float* __restrict__ cond,
                           const float* __restrict__ w1,
                           const float* __restrict__ w2) {
    __shared__ float sh[BATCH][HIDDEN + 1];
    __shared__ float satt[BATCH][KEXP];
    const int t = threadIdx.x;

    // phase 1: hidden = relu(cond @ w1^T) for all 64 b  (4096 dots)
#pragma unroll
    for (int i = 0; i < 16; ++i) {
        const int idx = t + 256 * i;
        const int b = idx >> 6, h = idx & 63;
        const float4* crow = (const float4*)(cond + b * CS);
        const float4* w1r  = (const float4*)(w1 + h * CS);
        float s0 = 0.0f, s1 = 0.0f;
#pragma unroll 8
        for (int q = 0; q < CS / 4; ++q) {
            float4 c4 = crow[q], w4 = w1r[q];
            s0 = fmaf(c4.x, w4.x, fmaf(c4.y, w4.y, s0));
            s1 = fmaf(c4.z, w4.z, fmaf(c4.w, w4.w, s1));
        }
        sh[b][h] = fmaxf(s0 + s1, 0.0f);
    }
    __syncthreads();

    // phase 2: logits (64 b x 4 k), temperature-scaled
    {
        const int b = t >> 2, k = t & 3;
        const float* w2r = w2 + k * HIDDEN;
        float s = 0.0f;
#pragma unroll 8
        for (int h = 0; h < HIDDEN; ++h) s = fmaf(sh[b][h], w2r[h], s);
        satt[b][k] = s * (1.0f / TEMP);
    }
    __syncthreads();

    // phase 3: softmax per b
    if (t < BATCH) {
        float l0 = satt[t][0], l1 = satt[t][1], l2 = satt[t][2], l3 = satt[t][3];
        float m = fmaxf(fmaxf(l0, l1), fmaxf(l2, l3));
        float e0 = expf(l0 - m), e1 = expf(l1 - m), e2 = expf(l2 - m), e3 = expf(l3 - m);
        float inv = 1.0f / (e0 + e1 + e2 + e3);
        satt[t][0] = e0 * inv; satt[t][1] = e1 * inv;
        satt[t][2] = e2 * inv; satt[t][3] = e3 * inv;
    }
    __syncthreads();
    if (blockIdx.x == 0) g_att[t] = satt[t >> 2][t & 3];   // 256 values

    // phase 4: weight mixing
    const int idx = blockIdx.x * 256 + t;             // 0 .. 3*4*256*8-1
    const int c8  = idx & 7;                          // 8-ci group
    const int o   = (idx >> 3) & 255;
    const int cbi = (idx >> 11) & 3;
    const int kh  = idx >> 13;                        // 0..2
    const int ci0 = cbi * CCH + 8 * c8;

    float w[KEXP][8];
#pragma unroll
    for (int k = 0; k < KEXP; ++k) {
        const float* wp = weight + (((size_t)(k * COUT + o) * CIN + ci0) * 3 + kh) * 3 + 1;
#pragma unroll
        for (int c = 0; c < 8; ++c) w[k][c] = wp[c * 9];
    }

    const size_t obase = (((size_t)kh * NCB + cbi) * COUT + o) * CCH + 8 * c8;
    for (int b = 0; b < BATCH; ++b) {
        float a0 = satt[b][0], a1 = satt[b][1], a2 = satt[b][2], a3 = satt[b][3];
        __half2 hv[4];
#pragma unroll
        for (int p = 0; p < 4; ++p) {
            float v0 = a0 * w[0][2*p]   + a1 * w[1][2*p]   + a2 * w[2][2*p]   + a3 * w[3][2*p];
            float v1 = a0 * w[0][2*p+1] + a1 * w[1][2*p+1] + a2 * w[2][2*p+1] + a3 * w[3][2*p+1];
            hv[p] = __floats2half2_rn(v0, v1);
        }
        *(uint4*)(g_wa + (size_t)b * WA_BSTRIDE + obase) = *(uint4*)hv;
    }
}

// ---------------------------------------------------------------------------
// Kernel 2: wmma fp16 conv. grid (8 h-tiles, 2 o-tiles, 64 b), 256 threads.
// 8 warps, 32x64 warp tiles, triple-buffered A (R10-proven config).
// ---------------------------------------------------------------------------
__global__ void __launch_bounds__(256, 2)
conv_kernel(const float* __restrict__ x,
            const float* __restrict__ bias,
            float* __restrict__ out) {
    extern __shared__ char smem[];
    const uint32_t sb = smem_u32(smem);
    const int tid = threadIdx.x;
    const int wid = tid >> 5;
    const int lid = tid & 31;
    const int hb  = blockIdx.x * TN;
    const int ob  = blockIdx.y * TM;
    const int b   = blockIdx.z;
    const int wm  = wid >> 1;     // 0..3 -> 32 o-rows
    const int wn  = wid & 1;      // 0..1 -> 64 h-cols

    const float* xb = x + (size_t)b * CIN * LEN;
    float* x_s = (float*)(smem + SM_X);

    auto issue_A = [&](int j) {
        const uint32_t bufoff = SM_ABUF(j % 3);
        const int cbi = j / 3;
        const int kh  = j - 3 * cbi;
        const uint4* gs = (const uint4*)(g_wa +
            ((((size_t)b * 3 + kh) * NCB + cbi) * COUT + ob) * CCH);
#pragma unroll
        for (int t = 0; t < 4; ++t) {
            int idx = tid + t * 256;          // 1024 chunks = 128 rows x 8
            int r = idx >> 3, c = idx & 7;
            cpa16(sb + bufoff + r * 144 + c * 16, gs + idx);
        }
    };
    auto issue_X = [&](int cbi) {
#pragma unroll
        for (int t = 0; t < 8; ++t) {
            int idx = tid + t * 256;          // 2048 chunks = 64 rows x 32
            int r = idx >> 5, c = idx & 31;
            cpa16(sb + SM_X + r * (XW * 4) + c * 16,
                  xb + (cbi * CCH + r) * LEN + hb + c * 4);
        }
        if (tid < 128) {                      // halo slots (plain STS)
            int r = tid & 63, side = tid >> 6;
            int h = side ? (hb + 128) : (hb - 1);
            float v = ((unsigned)h < (unsigned)LEN) ? xb[(cbi * CCH + r) * LEN + h] : 0.0f;
            x_s[r * XW + (side ? 128 : 129)] = v;
        }
    };

    // prologue groups: g0={A0,X0}, g1={A1}
    issue_A(0);
    issue_X(0);
    CP_COMMIT();
    issue_A(1);
    CP_COMMIT();

    // ---- accumulators + exact-bias K=16 GEMM term (tiles overlay B region) ----
    wmma::fragment<wmma::accumulator, 16, 16, 16, float> acc[2][4];
#pragma unroll
    for (int mt = 0; mt < 2; ++mt)
#pragma unroll
        for (int nt = 0; nt < 4; ++nt) wmma::fill_fragment(acc[mt][nt], 0.0f);

    for (int i = tid; i < 12288 / 4; i += 256)
        ((uint32_t*)(smem + SM_ABH))[i] = 0;
    __syncthreads();
    if (tid < 128) {
        const int o = ob + tid;
        const float* a = g_att + b * KEXP;
        float bm = 0.0f;
#pragma unroll
        for (int k = 0; k < KEXP; ++k) bm = fmaf(a[k], bias[k * COUT + o], bm);
        __half h = __float2half_rn(bm);
        __half* hA = (__half*)(smem + SM_ABH);
        __half* hB = (__half*)(smem + SM_BB);
        hA[tid * BBSTR + 0] = h;
        hA[tid * BBSTR + 1] = __float2half_rn(bm - __half2float(h));
        hB[tid * BBSTR + 0] = __float2half_rn(1.0f);
        hB[tid * BBSTR + 1] = __float2half_rn(1.0f);
    }
    __syncthreads();
    {
        wmma::fragment<wmma::matrix_a, 16, 16, 16, __half, wmma::row_major> fa;
        wmma::fragment<wmma::matrix_b, 16, 16, 16, __half, wmma::col_major> fb[4];
#pragma unroll
        for (int nt = 0; nt < 4; ++nt)
            wmma::load_matrix_sync(fb[nt],
                (const __half*)(smem + SM_BB) + (wn * 64 + nt * 16) * BBSTR, BBSTR);
#pragma unroll
        for (int mt = 0; mt < 2; ++mt) {
            wmma::load_matrix_sync(fa,
                (const __half*)(smem + SM_ABH) + (wm * 32 + mt * 16) * BBSTR, BBSTR);
#pragma unroll
            for (int nt = 0; nt < 4; ++nt)
                wmma::mma_sync(acc[mt][nt], fa, fb[nt], acc[mt][nt]);
        }
    }
    __syncthreads();           // bias tiles dead -> B region reusable

    CP_WAIT(1);                // g0 done: A0 + X0 resident (g1 may pend)
    __syncthreads();

    // ---- mainloop ----
    for (int cbi = 0; cbi < NCB; ++cbi) {
        // build B tile [n][ci] fp16 from x_s (conflict-free both sides)
        {
            const int nl = lid >> 2, cl = lid & 3;
            for (int job = wid; job < 8 * 17; job += 8) {
                const int cpb  = job / 17;
                const int nblk = job - 17 * cpb;
                const int n  = nblk * 8 + nl;
                const int cp = cpb * 4 + cl;          // ci pair 0..31
                if (n < 130) {
                    const int jj = (n == 0) ? 129 : (n - 1);
                    float v0 = x_s[(2 * cp    ) * XW + jj];
                    float v1 = x_s[(2 * cp + 1) * XW + jj];
                    *(__half2*)(smem + SM_B + n * 144 + cp * 4) =
                        __floats2half2_rn(v0, v1);
                }
            }
        }
        __syncthreads();

        for (int kh = 0; kh < 3; ++kh) {
            const int j = cbi * 3 + kh;
            if (j + 2 < NTILE) issue_A(j + 2);
            if (kh == 0 && cbi + 1 < NCB) issue_X(cbi + 1);
            CP_COMMIT();                 // group g_{j+2}
            CP_WAIT(2);                  // groups <= g_j done: A(j) resident
            __syncthreads();

            const __half* A  = (const __half*)(smem + SM_ABUF(j % 3));
            const __half* Bp = (const __half*)(smem + SM_B);

#pragma unroll
            for (int ks = 0; ks < 4; ++ks) {
                wmma::fragment<wmma::matrix_a, 16, 16, 16, __half, wmma::row_major> fa[2];
                wmma::fragment<wmma::matrix_b, 16, 16, 16, __half, wmma::col_major> fb[4];
#pragma unroll
                for (int mt = 0; mt < 2; ++mt)
                    wmma::load_matrix_sync(fa[mt], A + (wm * 32 + mt * 16) * ASTR + ks * 16, ASTR);
#pragma unroll
                for (int nt = 0; nt < 4; ++nt)
                    wmma::load_matrix_sync(fb[nt], Bp + (wn * 64 + nt * 16 + kh) * BSTR + ks * 16, BSTR);
#pragma unroll
                for (int mt = 0; mt < 2; ++mt)
#pragma unroll
                    for (int nt = 0; nt < 4; ++nt)
                        wmma::mma_sync(acc[mt][nt], fa[mt], fb[nt], acc[mt][nt]);
            }
            __syncthreads();   // frag reads done: buf (j)%3 free for reuse
        }
    }

    // ---- epilogue: bias already in acc; direct global store ----
    float* op = out + ((size_t)(b * COUT + ob + wm * 32)) * LEN + hb + wn * 64;
#pragma unroll
    for (int mt = 0; mt < 2; ++mt)
#pragma unroll
        for (int nt = 0; nt < 4; ++nt)
            wmma::store_matrix_sync(op + (size_t)mt * 16 * LEN + nt * 16,
                                    acc[mt][nt], LEN, wmma::mem_row_major);
}

// ---------------------------------------------------------------------------
extern "C" void kernel_launch(void* const* d_in, const int* in_sizes, int n_in,
                              void* d_out, int out_size) {
    const float* x      = (const float*)d_in[0];   // (64,256,1024,1)
    const float* cond   = (const float*)d_in[1];   // (64,256)
    const float* w1     = (const float*)d_in[2];   // (64,256)
    const float* w2     = (const float*)d_in[3];   // (4,64)
    const float* weight = (const float*)d_in[4];   // (4,256,256,3,3)
    const float* bias   = (const float*)d_in[5];   // (4,256)
    float* out = (float*)d_out;                    // (64,256,1024,1)

    static int attr_set = 0;
    if (!attr_set) {
        cudaFuncSetAttribute(conv_kernel,
                             cudaFuncAttributeMaxDynamicSharedMemorySize, SM_TOTAL);
        attr_set = 1;
    }

    mix_kernel<<<(3 * NCB * COUT * 8) / 256, 256>>>(weight, cond, w1, w2);
    conv_kernel<<<dim3(LEN / TN, COUT / TM, BATCH), 256, SM_TOTAL>>>(x, bias, out);
}

// round 14
// speedup vs baseline: 1.4904x; 1.4904x over previous
#include <cuda_runtime.h>
#include <cuda_fp16.h>
#include <mma.h>
#include <cstdint>

using namespace nvcuda;

// DynamicConv: B=64, CIN=COUT=256, K=4 experts, 3x3 kernel on (L=1024 x 1).
// Width==1 + padding 1 => only kw=1 column contributes: per-batch GEMM
//   C[o,h] = sum_{ci,kh} Wagg[b][o,ci,kh] * x[b][ci,h-1+kh]   (M=256,N=1024,K=768)
// R13: 3-kernel split restored (R12 fusion post-mortem: I$ bloat + spills).
//      Conv: B tile built DIRECTLY from global x (coalesced LDG -> fp16 STS),
//      x_s staging eliminated (-16% smem crossbar traffic). smem 74.9 KB.

#define BATCH   64
#define CIN     256
#define COUT    256
#define CS      256
#define KEXP    4
#define HIDDEN  64
#define LEN     1024
#define TEMP    30.0f

#define TM      128            // o per CTA
#define TN      128            // h per CTA
#define CCH     64             // ci per K-chunk
#define NCB     (CIN / CCH)    // 4
#define NTILE   (3 * NCB)      // 12

#define ASTR    72             // fp16 A row stride (144 B)
#define BSTR    72             // fp16 B row stride
#define BBSTR   24             // bias tile stride

// SMEM layout (bytes)
#define SM_ABUF(i) ((uint32_t)(18432u * (i)))   // 3 x 128x144
#define SM_B     55296          // B 136x144 = 19584
#define SM_TOTAL 74880
// bias tiles overlay B region (pre-mainloop only)
#define SM_ABH   SM_B
#define SM_BB    (SM_B + 6144)

__device__ float g_att[BATCH * KEXP];
__device__ float g_bmix[BATCH * COUT];
// Wagg fp16: [b][kh][cbi][o(256)][ci(64)]
#define WA_BSTRIDE (3 * NCB * COUT * CCH)   // 196608
__device__ __half g_wa[BATCH * WA_BSTRIDE];

__device__ __forceinline__ uint32_t smem_u32(const void* p) {
    uint32_t a;
    asm("{ .reg .u64 t; cvta.to.shared.u64 t, %1; cvt.u32.u64 %0, t; }" : "=r"(a) : "l"(p));
    return a;
}
__device__ __forceinline__ void cpa16(uint32_t d, const void* s) {
    asm volatile("cp.async.cg.shared.global [%0], [%1], 16;" :: "r"(d), "l"(s));
}
#define CP_COMMIT()  asm volatile("cp.async.commit_group;" ::: "memory")
#define CP_WAIT(n)   asm volatile("cp.async.wait_group %0;" :: "n"(n) : "memory")

// ---------------------------------------------------------------------------
// Kernel 1: routing MLP + softmax + mixed bias.
// ---------------------------------------------------------------------------
__global__ void routing_kernel(const float* __restrict__ cond,
                               const float* __restrict__ w1,
                               const float* __restrict__ w2,
                               const float* __restrict__ bias) {
    __shared__ float sh[HIDDEN];
    __shared__ float sl[KEXP];
    __shared__ float satt[KEXP];
    const int b = blockIdx.x;
    const int t = threadIdx.x;

    if (t < HIDDEN) {
        const float4* crow = (const float4*)(cond + b * CS);
        const float4* w1r  = (const float4*)(w1 + t * CS);
        float s0 = 0.0f, s1 = 0.0f;
#pragma unroll 8
        for (int i = 0; i < CS / 4; ++i) {
            float4 c4 = crow[i], w4 = w1r[i];
            s0 = fmaf(c4.x, w4.x, fmaf(c4.y, w4.y, s0));
            s1 = fmaf(c4.z, w4.z, fmaf(c4.w, w4.w, s1));
        }
        sh[t] = fmaxf(s0 + s1, 0.0f);
    }
    __syncthreads();
    if (t < KEXP) {
        const float* w2r = w2 + t * HIDDEN;
        float s = 0.0f;
#pragma unroll 8
        for (int i = 0; i < HIDDEN; ++i) s = fmaf(sh[i], w2r[i], s);
        sl[t] = s * (1.0f / TEMP);
    }
    __syncthreads();
    if (t == 0) {
        float m = sl[0];
#pragma unroll
        for (int k = 1; k < KEXP; ++k) m = fmaxf(m, sl[k]);
        float e[KEXP], sum = 0.0f;
#pragma unroll
        for (int k = 0; k < KEXP; ++k) { e[k] = expf(sl[k] - m); sum += e[k]; }
        float inv = 1.0f / sum;
#pragma unroll
        for (int k = 0; k < KEXP; ++k) {
            satt[k] = e[k] * inv;
            g_att[b * KEXP + k] = e[k] * inv;
        }
    }
    __syncthreads();
    {
        float v = 0.0f;
#pragma unroll
        for (int k = 0; k < KEXP; ++k) v = fmaf(satt[k], bias[k * COUT + t], v);
        g_bmix[b * COUT + t] = v;
    }
}

// ---------------------------------------------------------------------------
// Kernel 2: mix experts -> g_wa fp16. Thread = (kh,cbi,o,8-ci group).
// 16B coalesced stores, 64-batch register loop.
// ---------------------------------------------------------------------------
__global__ void mix_kernel(const float* __restrict__ weight) {
    const int idx = blockIdx.x * 256 + threadIdx.x;   // 0 .. 3*4*256*8-1
    const int c8  = idx & 7;                          // 8-ci group
    const int o   = (idx >> 3) & 255;
    const int cbi = (idx >> 11) & 3;
    const int kh  = idx >> 13;                        // 0..2
    const int ci0 = cbi * CCH + 8 * c8;

    float w[KEXP][8];
#pragma unroll
    for (int k = 0; k < KEXP; ++k) {
        const float* wp = weight + (((size_t)(k * COUT + o) * CIN + ci0) * 3 + kh) * 3 + 1;
#pragma unroll
        for (int c = 0; c < 8; ++c) w[k][c] = wp[c * 9];
    }

    const size_t obase = (((size_t)kh * NCB + cbi) * COUT + o) * CCH + 8 * c8;
    for (int b = 0; b < BATCH; ++b) {
        const float* a = g_att + b * KEXP;
        float a0 = a[0], a1 = a[1], a2 = a[2], a3 = a[3];
        __half2 hv[4];
#pragma unroll
        for (int p = 0; p < 4; ++p) {
            float v0 = a0 * w[0][2*p]   + a1 * w[1][2*p]   + a2 * w[2][2*p]   + a3 * w[3][2*p];
            float v1 = a0 * w[0][2*p+1] + a1 * w[1][2*p+1] + a2 * w[2][2*p+1] + a3 * w[3][2*p+1];
            hv[p] = __floats2half2_rn(v0, v1);
        }
        *(uint4*)(g_wa + (size_t)b * WA_BSTRIDE + obase) = *(uint4*)hv;
    }
}

// ---------------------------------------------------------------------------
// Kernel 3: wmma fp16 conv. grid (8 h-tiles, 2 o-tiles, 64 b), 256 threads.
// 8 warps, 32x64 warp tiles, triple-buffered A, B built direct from global.
// ---------------------------------------------------------------------------
__global__ void __launch_bounds__(256, 2)
conv_kernel(const float* __restrict__ x, float* __restrict__ out) {
    extern __shared__ char smem[];
    const uint32_t sb = smem_u32(smem);
    const int tid = threadIdx.x;
    const int wid = tid >> 5;
    const int lid = tid & 31;
    const int hb  = blockIdx.x * TN;
    const int ob  = blockIdx.y * TM;
    const int b   = blockIdx.z;
    const int wm  = wid >> 1;     // 0..3 -> 32 o-rows
    const int wn  = wid & 1;      // 0..1 -> 64 h-cols

    const float* xb = x + (size_t)b * CIN * LEN;

    auto issue_A = [&](int j) {
        const uint32_t bufoff = SM_ABUF(j % 3);
        const int cbi = j / 3;
        const int kh  = j - 3 * cbi;
        const uint4* gs = (const uint4*)(g_wa +
            ((((size_t)b * 3 + kh) * NCB + cbi) * COUT + ob) * CCH);
#pragma unroll
        for (int t = 0; t < 4; ++t) {
            int idx = tid + t * 256;          // 1024 chunks = 128 rows x 8
            int r = idx >> 3, c = idx & 7;
            cpa16(sb + bufoff + r * 144 + c * 16, gs + idx);
        }
    };

    // prologue groups: g0={A0}, g1={A1}
    issue_A(0);
    CP_COMMIT();
    issue_A(1);
    CP_COMMIT();

    // ---- accumulators + exact-bias K=16 GEMM term (tiles overlay B region) ----
    wmma::fragment<wmma::accumulator, 16, 16, 16, float> acc[2][4];
#pragma unroll
    for (int mt = 0; mt < 2; ++mt)
#pragma unroll
        for (int nt = 0; nt < 4; ++nt) wmma::fill_fragment(acc[mt][nt], 0.0f);

    for (int i = tid; i < 12288 / 4; i += 256)
        ((uint32_t*)(smem + SM_ABH))[i] = 0;
    __syncthreads();
    if (tid < 128) {
        float bm = g_bmix[b * COUT + ob + tid];
        __half h = __float2half_rn(bm);
        __half* hA = (__half*)(smem + SM_ABH);
        __half* hB = (__half*)(smem + SM_BB);
        hA[tid * BBSTR + 0] = h;
        hA[tid * BBSTR + 1] = __float2half_rn(bm - __half2float(h));
        hB[tid * BBSTR + 0] = __float2half_rn(1.0f);
        hB[tid * BBSTR + 1] = __float2half_rn(1.0f);
    }
    __syncthreads();
    {
        wmma::fragment<wmma::matrix_a, 16, 16, 16, __half, wmma::row_major> fa;
        wmma::fragment<wmma::matrix_b, 16, 16, 16, __half, wmma::col_major> fb[4];
#pragma unroll
        for (int nt = 0; nt < 4; ++nt)
            wmma::load_matrix_sync(fb[nt],
                (const __half*)(smem + SM_BB) + (wn * 64 + nt * 16) * BBSTR, BBSTR);
#pragma unroll
        for (int mt = 0; mt < 2; ++mt) {
            wmma::load_matrix_sync(fa,
                (const __half*)(smem + SM_ABH) + (wm * 32 + mt * 16) * BBSTR, BBSTR);
#pragma unroll
            for (int nt = 0; nt < 4; ++nt)
                wmma::mma_sync(acc[mt][nt], fa, fb[nt], acc[mt][nt]);
        }
    }
    __syncthreads();           // bias tiles dead -> B region reusable

    CP_WAIT(1);                // g0 done: A0 resident (g1 may pend)
    __syncthreads();

    // ---- mainloop ----
    for (int cbi = 0; cbi < NCB; ++cbi) {
        // ---- build B [n][ci] fp16 DIRECTLY from global x ----
        // body rows n=1..128: B[n][ci] = x[ci][hb+n-1]; warp = fixed ci,
        // lanes read consecutive h (coalesced LDG.32). hb+127 <= 1023: no guard.
        {
#pragma unroll
            for (int t = 0; t < 8; ++t) {
                const int ci = wid * 8 + t;
                const float* xr = xb + (cbi * CCH + ci) * LEN + hb;
#pragma unroll
                for (int i = 0; i < 4; ++i) {
                    const int hl = lid + 32 * i;   // 0..127
                    *(__half*)(smem + SM_B + (hl + 1) * 144 + ci * 2) =
                        __float2half_rn(xr[hl]);
                }
            }
            // halo rows n=0 (h=hb-1) and n=129 (h=hb+128)
            if (tid < 128) {
                const int ci = tid & 63, side = tid >> 6;
                const int h = side ? (hb + 128) : (hb - 1);
                float v = ((unsigned)h < (unsigned)LEN)
                              ? xb[(cbi * CCH + ci) * LEN + h] : 0.0f;
                const int n = side ? 129 : 0;
                *(__half*)(smem + SM_B + n * 144 + ci * 2) = __float2half_rn(v);
            }
        }
        __syncthreads();

        for (int kh = 0; kh < 3; ++kh) {
            const int j = cbi * 3 + kh;
            if (j + 2 < NTILE) issue_A(j + 2);
            CP_COMMIT();                 // group g_{j+2}
            CP_WAIT(2);                  // groups <= g_j done: A(j) resident
            __syncthreads();

            const __half* A  = (const __half*)(smem + SM_ABUF(j % 3));
            const __half* Bp = (const __half*)(smem + SM_B);

#pragma unroll
            for (int ks = 0; ks < 4; ++ks) {
                wmma::fragment<wmma::matrix_a, 16, 16, 16, __half, wmma::row_major> fa[2];
                wmma::fragment<wmma::matrix_b, 16, 16, 16, __half, wmma::col_major> fb[4];
#pragma unroll
                for (int mt = 0; mt < 2; ++mt)
                    wmma::load_matrix_sync(fa[mt], A + (wm * 32 + mt * 16) * ASTR + ks * 16, ASTR);
#pragma unroll
                for (int nt = 0; nt < 4; ++nt)
                    wmma::load_matrix_sync(fb[nt], Bp + (wn * 64 + nt * 16 + kh) * BSTR + ks * 16, BSTR);
#pragma unroll
                for (int mt = 0; mt < 2; ++mt)
#pragma unroll
                    for (int nt = 0; nt < 4; ++nt)
                        wmma::mma_sync(acc[mt][nt], fa[mt], fb[nt], acc[mt][nt]);
            }
            __syncthreads();   // frag reads done: A buf free for reuse, B safe at next cbi
        }
    }

    // ---- epilogue: bias already in acc; direct global store ----
    float* op = out + ((size_t)(b * COUT + ob + wm * 32)) * LEN + hb + wn * 64;
#pragma unroll
    for (int mt = 0; mt < 2; ++mt)
#pragma unroll
        for (int nt = 0; nt < 4; ++nt)
            wmma::store_matrix_sync(op + (size_t)mt * 16 * LEN + nt * 16,
                                    acc[mt][nt], LEN, wmma::mem_row_major);
}

// ---------------------------------------------------------------------------
extern "C" void kernel_launch(void* const* d_in, const int* in_sizes, int n_in,
                              void* d_out, int out_size) {
    const float* x      = (const float*)d_in[0];   // (64,256,1024,1)
    const float* cond   = (const float*)d_in[1];   // (64,256)
    const float* w1     = (const float*)d_in[2];   // (64,256)
    const float* w2     = (const float*)d_in[3];   // (4,64)
    const float* weight = (const float*)d_in[4];   // (4,256,256,3,3)
    const float* bias   = (const float*)d_in[5];   // (4,256)
    float* out = (float*)d_out;                    // (64,256,1024,1)

    static int attr_set = 0;
    if (!attr_set) {
        cudaFuncSetAttribute(conv_kernel,
                             cudaFuncAttributeMaxDynamicSharedMemorySize, SM_TOTAL);
        attr_set = 1;
    }

    routing_kernel<<<BATCH, 256>>>(cond, w1, w2, bias);
    mix_kernel<<<(3 * NCB * COUT * 8) / 256, 256>>>(weight);
    conv_kernel<<<dim3(LEN / TN, COUT / TM, BATCH), 256, SM_TOTAL>>>(x, out);
}

// round 15
// speedup vs baseline: 2.3619x; 1.5847x over previous
#include <cuda_runtime.h>
#include <cuda_fp16.h>
#include <mma.h>
#include <cstdint>

using namespace nvcuda;

// DynamicConv: B=64, CIN=COUT=256, K=4 experts, 3x3 kernel on (L=1024 x 1).
// Width==1 + padding 1 => only kw=1 column contributes: per-batch GEMM
//   C[o,h] = sum_{ci,kh} Wagg[b][o,ci,kh] * x[b][ci,h-1+kh]   (M=256,N=1024,K=768)
// R14: x pre-transposed to fp16 g_xt[b][h][ci] (inside mix kernel, role-split
//      grid) -> conv B tile is a pure cp.async copy (no in-conv transpose).
//      Conv: 4 A bufs + 2 B bufs, all cp.async, ONE barrier per iteration.

#define BATCH   64
#define CIN     256
#define COUT    256
#define CS      256
#define KEXP    4
#define HIDDEN  64
#define LEN     1024
#define TEMP    30.0f

#define TM      128            // o per CTA
#define TN      128            // h per CTA
#define CCH     64             // ci per K-chunk
#define NCB     (CIN / CCH)    // 4
#define NTILE   (3 * NCB)      // 12

#define ASTR    72             // fp16 A row stride (144 B)
#define BSTR    72             // fp16 B row stride
#define BBSTR   24             // bias tile stride

#define MIXB    96             // mix blocks in prep kernel

// SMEM layout (bytes): A 4 x 18432 | B 2 x 19008
#define SM_ABUF(i) ((uint32_t)(18432u * (i)))
#define SM_B0    73728
#define SM_BBUF(i) ((uint32_t)(SM_B0 + 19008u * (i)))
#define SM_TOTAL (73728 + 2 * 19008)     // 111744
// bias tiles overlay B buf 1 (pre-mainloop only; B1 first written at iter 1)
#define SM_ABH   SM_BBUF(1)
#define SM_BB    (SM_ABH + 6144)

__device__ float g_att[BATCH * KEXP];
__device__ float g_bmix[BATCH * COUT];
// Wagg fp16: [b][kh][cbi][o(256)][ci(64)]
#define WA_BSTRIDE (3 * NCB * COUT * CCH)   // 196608
__device__ __align__(16) __half g_wa[BATCH * WA_BSTRIDE];
// x transposed fp16: [b][h(1024)][ci(256)]
__device__ __align__(16) __half g_xt[(size_t)BATCH * LEN * CIN];

__device__ __forceinline__ uint32_t smem_u32(const void* p) {
    uint32_t a;
    asm("{ .reg .u64 t; cvta.to.shared.u64 t, %1; cvt.u32.u64 %0, t; }" : "=r"(a) : "l"(p));
    return a;
}
__device__ __forceinline__ void cpa16(uint32_t d, const void* s) {
    asm volatile("cp.async.cg.shared.global [%0], [%1], 16;" :: "r"(d), "l"(s));
}
#define CP_COMMIT()  asm volatile("cp.async.commit_group;" ::: "memory")
#define CP_WAIT(n)   asm volatile("cp.async.wait_group %0;" :: "n"(n) : "memory")

// ---------------------------------------------------------------------------
// Kernel 1: routing MLP + softmax + mixed bias.
// ---------------------------------------------------------------------------
__global__ void routing_kernel(const float* __restrict__ cond,
                               const float* __restrict__ w1,
                               const float* __restrict__ w2,
                               const float* __restrict__ bias) {
    __shared__ float sh[HIDDEN];
    __shared__ float sl[KEXP];
    __shared__ float satt[KEXP];
    const int b = blockIdx.x;
    const int t = threadIdx.x;

    if (t < HIDDEN) {
        const float4* crow = (const float4*)(cond + b * CS);
        const float4* w1r  = (const float4*)(w1 + t * CS);
        float s0 = 0.0f, s1 = 0.0f;
#pragma unroll 8
        for (int i = 0; i < CS / 4; ++i) {
            float4 c4 = crow[i], w4 = w1r[i];
            s0 = fmaf(c4.x, w4.x, fmaf(c4.y, w4.y, s0));
            s1 = fmaf(c4.z, w4.z, fmaf(c4.w, w4.w, s1));
        }
        sh[t] = fmaxf(s0 + s1, 0.0f);
    }
    __syncthreads();
    if (t < KEXP) {
        const float* w2r = w2 + t * HIDDEN;
        float s = 0.0f;
#pragma unroll 8
        for (int i = 0; i < HIDDEN; ++i) s = fmaf(sh[i], w2r[i], s);
        sl[t] = s * (1.0f / TEMP);
    }
    __syncthreads();
    if (t == 0) {
        float m = sl[0];
#pragma unroll
        for (int k = 1; k < KEXP; ++k) m = fmaxf(m, sl[k]);
        float e[KEXP], sum = 0.0f;
#pragma unroll
        for (int k = 0; k < KEXP; ++k) { e[k] = expf(sl[k] - m); sum += e[k]; }
        float inv = 1.0f / sum;
#pragma unroll
        for (int k = 0; k < KEXP; ++k) {
            satt[k] = e[k] * inv;
            g_att[b * KEXP + k] = e[k] * inv;
        }
    }
    __syncthreads();
    {
        float v = 0.0f;
#pragma unroll
        for (int k = 0; k < KEXP; ++k) v = fmaf(satt[k], bias[k * COUT + t], v);
        g_bmix[b * COUT + t] = v;
    }
}

// ---------------------------------------------------------------------------
// Kernel 2 (prep): role-split grid.
//   blocks [0, 96)        : mix experts -> g_wa fp16
//   blocks [96, 96+4096)  : transpose x -> g_xt[b][h][ci] fp16 (64x64 tiles)
// ---------------------------------------------------------------------------
__global__ void prep_kernel(const float* __restrict__ weight,
                            const float* __restrict__ x) {
    __shared__ float s[64][65];
    const int t = threadIdx.x;

    if (blockIdx.x < MIXB) {
        // ---- mix path: thread = (kh,cbi,o,8-ci group) ----
        const int idx = blockIdx.x * 256 + t;             // 0 .. 3*4*256*8-1
        const int c8  = idx & 7;
        const int o   = (idx >> 3) & 255;
        const int cbi = (idx >> 11) & 3;
        const int kh  = idx >> 13;
        const int ci0 = cbi * CCH + 8 * c8;

        float w[KEXP][8];
#pragma unroll
        for (int k = 0; k < KEXP; ++k) {
            const float* wp = weight + (((size_t)(k * COUT + o) * CIN + ci0) * 3 + kh) * 3 + 1;
#pragma unroll
            for (int c = 0; c < 8; ++c) w[k][c] = wp[c * 9];
        }

        const size_t obase = (((size_t)kh * NCB + cbi) * COUT + o) * CCH + 8 * c8;
        for (int b = 0; b < BATCH; ++b) {
            const float* a = g_att + b * KEXP;
            float a0 = a[0], a1 = a[1], a2 = a[2], a3 = a[3];
            __half2 hv[4];
#pragma unroll
            for (int p = 0; p < 4; ++p) {
                float v0 = a0 * w[0][2*p]   + a1 * w[1][2*p]   + a2 * w[2][2*p]   + a3 * w[3][2*p];
                float v1 = a0 * w[0][2*p+1] + a1 * w[1][2*p+1] + a2 * w[2][2*p+1] + a3 * w[3][2*p+1];
                hv[p] = __floats2half2_rn(v0, v1);
            }
            *(uint4*)(g_wa + (size_t)b * WA_BSTRIDE + obase) = *(uint4*)hv;
        }
    } else {
        // ---- transpose path: tile (b, 64 h, 64 ci) ----
        const int tb  = blockIdx.x - MIXB;                // 0..4095
        const int b   = tb >> 6;
        const int hti = (tb >> 2) & 15;
        const int cti = tb & 3;
        const int h0  = hti * 64;
        const int ci0 = cti * 64;

        // read: rows = ci (coalesced along h)
#pragma unroll
        for (int q = 0; q < 16; ++q) {
            const int idx = t + q * 256;
            const int r = idx >> 6, c = idx & 63;         // r = ci-local, c = h-local
            s[r][c] = x[((size_t)(b * CIN + ci0 + r)) * LEN + h0 + c];
        }
        __syncthreads();
        // write: rows = h (coalesced along ci); transposed smem read conflict-free (pad 65)
#pragma unroll
        for (int q = 0; q < 16; ++q) {
            const int idx = t + q * 256;
            const int r2 = idx >> 6, c2 = idx & 63;       // r2 = h-local, c2 = ci-local
            g_xt[((size_t)b * LEN + h0 + r2) * CIN + ci0 + c2] = __float2half_rn(s[c2][r2]);
        }
    }
}

// ---------------------------------------------------------------------------
// Kernel 3: wmma fp16 conv. grid (8 h-tiles, 2 o-tiles, 64 b), 256 threads.
// 8 warps, 32x64 warp tiles. 4 A bufs + 2 B bufs, all cp.async, 1 barrier/iter.
// ---------------------------------------------------------------------------
__global__ void __launch_bounds__(256, 2)
conv_kernel(float* __restrict__ out) {
    extern __shared__ char smem[];
    const uint32_t sb = smem_u32(smem);
    const int tid = threadIdx.x;
    const int wid = tid >> 5;
    const int hb  = blockIdx.x * TN;
    const int ob  = blockIdx.y * TM;
    const int b   = blockIdx.z;
    const int wm  = wid >> 1;     // 0..3 -> 32 o-rows
    const int wn  = wid & 1;      // 0..1 -> 64 h-cols

    auto issue_A = [&](int j) {
        const uint32_t bufoff = SM_ABUF(j & 3);
        const int cbi = j / 3;
        const int kh  = j - 3 * cbi;
        const uint4* gs = (const uint4*)(g_wa +
            ((((size_t)b * 3 + kh) * NCB + cbi) * COUT + ob) * CCH);
#pragma unroll
        for (int t = 0; t < 4; ++t) {
            int idx = tid + t * 256;          // 1024 chunks = 128 rows x 8
            int r = idx >> 3, c = idx & 7;
            cpa16(sb + bufoff + r * 144 + c * 16, gs + idx);
        }
    };
    // B tile for chunk cbi2: rows n=0..129 <- g_xt[b][hb-1+n][cbi2*64 .. +64)
    auto issue_B = [&](int cbi2) {
        const uint32_t bufoff = SM_BBUF(cbi2 & 1);
        const __half* gx = g_xt + (size_t)b * LEN * CIN + cbi2 * CCH;
#pragma unroll
        for (int t = 0; t < 5; ++t) {
            int idx = tid + t * 256;          // need 1040 chunks
            if (idx < 1040) {
                int n = idx >> 3, c = idx & 7;
                int h = hb - 1 + n;
                uint32_t d = sb + bufoff + n * 144 + c * 16;
                if ((unsigned)h < (unsigned)LEN)
                    cpa16(d, gx + (size_t)h * CIN + c * 8);
                else
                    *(uint4*)(smem + bufoff + n * 144 + c * 16) = make_uint4(0, 0, 0, 0);
            }
        }
    };

    // prologue groups: g0={A0,B0}, g1={A1}
    issue_A(0);
    issue_B(0);
    CP_COMMIT();
    issue_A(1);
    CP_COMMIT();

    // ---- accumulators + exact-bias K=16 GEMM term (tiles overlay B buf 1) ----
    wmma::fragment<wmma::accumulator, 16, 16, 16, float> acc[2][4];
#pragma unroll
    for (int mt = 0; mt < 2; ++mt)
#pragma unroll
        for (int nt = 0; nt < 4; ++nt) wmma::fill_fragment(acc[mt][nt], 0.0f);

    for (int i = tid; i < 12288 / 4; i += 256)
        ((uint32_t*)(smem + SM_ABH))[i] = 0;
    __syncthreads();
    if (tid < 128) {
        float bm = g_bmix[b * COUT + ob + tid];
        __half h = __float2half_rn(bm);
        __half* hA = (__half*)(smem + SM_ABH);
        __half* hB = (__half*)(smem + SM_BB);
        hA[tid * BBSTR + 0] = h;
        hA[tid * BBSTR + 1] = __float2half_rn(bm - __half2float(h));
        hB[tid * BBSTR + 0] = __float2half_rn(1.0f);
        hB[tid * BBSTR + 1] = __float2half_rn(1.0f);
    }
    __syncthreads();
    {
        wmma::fragment<wmma::matrix_a, 16, 16, 16, __half, wmma::row_major> fa;
        wmma::fragment<wmma::matrix_b, 16, 16, 16, __half, wmma::col_major> fb[4];
#pragma unroll
        for (int nt = 0; nt < 4; ++nt)
            wmma::load_matrix_sync(fb[nt],
                (const __half*)(smem + SM_BB) + (wn * 64 + nt * 16) * BBSTR, BBSTR);
#pragma unroll
        for (int mt = 0; mt < 2; ++mt) {
            wmma::load_matrix_sync(fa,
                (const __half*)(smem + SM_ABH) + (wm * 32 + mt * 16) * BBSTR, BBSTR);
#pragma unroll
            for (int nt = 0; nt < 4; ++nt)
                wmma::mma_sync(acc[mt][nt], fa, fb[nt], acc[mt][nt]);
        }
    }

    CP_WAIT(1);                // g0 done: A0 + B0 resident (g1 may pend)
    __syncthreads();           // also: bias-tile reads done before B1 write at j=1

    // ---- mainloop: ONE barrier per iteration ----
    for (int j = 0; j < NTILE; ++j) {
        const int cbi = j / 3;
        const int kh  = j - 3 * cbi;

        if (j + 2 < NTILE) issue_A(j + 2);
        if (kh == 1 && cbi + 1 < NCB) issue_B(cbi + 1);   // at kh==1: no reader
                                                          // of buf (cbi+1)&1 in window
        CP_COMMIT();                 // group g_{j+2}
        CP_WAIT(2);                  // groups <= g_j done: A(j), B(cbi) resident
        __syncthreads();

        const __half* A  = (const __half*)(smem + SM_ABUF(j & 3));
        const __half* Bp = (const __half*)(smem + SM_BBUF(cbi & 1));

#pragma unroll
        for (int ks = 0; ks < 4; ++ks) {
            wmma::fragment<wmma::matrix_a, 16, 16, 16, __half, wmma::row_major> fa[2];
            wmma::fragment<wmma::matrix_b, 16, 16, 16, __half, wmma::col_major> fb[4];
#pragma unroll
            for (int mt = 0; mt < 2; ++mt)
                wmma::load_matrix_sync(fa[mt], A + (wm * 32 + mt * 16) * ASTR + ks * 16, ASTR);
#pragma unroll
            for (int nt = 0; nt < 4; ++nt)
                wmma::load_matrix_sync(fb[nt], Bp + (wn * 64 + nt * 16 + kh) * BSTR + ks * 16, BSTR);
#pragma unroll
            for (int mt = 0; mt < 2; ++mt)
#pragma unroll
                for (int nt = 0; nt < 4; ++nt)
                    wmma::mma_sync(acc[mt][nt], fa[mt], fb[nt], acc[mt][nt]);
        }
        // no trailing barrier: 4-deep A ring + 2-deep B ring make next issues safe
    }

    // ---- epilogue: bias already in acc; direct global store ----
    float* op = out + ((size_t)(b * COUT + ob + wm * 32)) * LEN + hb + wn * 64;
#pragma unroll
    for (int mt = 0; mt < 2; ++mt)
#pragma unroll
        for (int nt = 0; nt < 4; ++nt)
            wmma::store_matrix_sync(op + (size_t)mt * 16 * LEN + nt * 16,
                                    acc[mt][nt], LEN, wmma::mem_row_major);
}

// ---------------------------------------------------------------------------
extern "C" void kernel_launch(void* const* d_in, const int* in_sizes, int n_in,
                              void* d_out, int out_size) {
    const float* x      = (const float*)d_in[0];   // (64,256,1024,1)
    const float* cond   = (const float*)d_in[1];   // (64,256)
    const float* w1     = (const float*)d_in[2];   // (64,256)
    const float* w2     = (const float*)d_in[3];   // (4,64)
    const float* weight = (const float*)d_in[4];   // (4,256,256,3,3)
    const float* bias   = (const float*)d_in[5];   // (4,256)
    float* out = (float*)d_out;                    // (64,256,1024,1)

    static int attr_set = 0;
    if (!attr_set) {
        cudaFuncSetAttribute(conv_kernel,
                             cudaFuncAttributeMaxDynamicSharedMemorySize, SM_TOTAL);
        attr_set = 1;
    }

    routing_kernel<<<BATCH, 256>>>(cond, w1, w2, bias);
    prep_kernel<<<MIXB + BATCH * 16 * 4, 256>>>(weight, x);
    conv_kernel<<<dim3(LEN / TN, COUT / TM, BATCH), 256, SM_TOTAL>>>(out);
}